// round 13
// baseline (speedup 1.0000x reference)
#include <cuda_runtime.h>
#include <cuda_fp16.h>
#include <cstdint>

#define SLEN  1024
#define DM    4096
#define FF    14336
#define KVDIM 1024
#define RLORA 16
#define LSCALE 2.0f

// ---------------- scratch (device globals; no allocations) ----------------
__device__ float g_h[SLEN * DM];
__device__ float g_q[SLEN * DM];
__device__ float g_k[SLEN * KVDIM];
__device__ float g_v[SLEN * KVDIM];
__device__ float g_attn[SLEN * DM];
__device__ float g_res2[SLEN * DM];
__device__ float g_gate[SLEN * FF];
__device__ float g_up[SLEN * FF];
__device__ float g_tmp[SLEN * RLORA];

// fp16 mirrors
__device__ __half g_wq_h[DM * DM];
__device__ __half g_wk_h[KVDIM * DM];
__device__ __half g_wv_h[KVDIM * DM];
__device__ __half g_wo_h[DM * DM];
__device__ __half g_w1_h[FF * DM];
__device__ __half g_w3_h[FF * DM];
__device__ __half g_w2_h[DM * FF];
__device__ __half g_h_h[SLEN * DM];
__device__ __half g_attn_h[SLEN * DM];
__device__ __half g_gu_h[SLEN * FF];

// ======================= helpers =======================
__device__ __forceinline__ uint32_t smem_u32(const void* p) {
    uint32_t a;
    asm("{ .reg .u64 t; cvta.to.shared.u64 t, %1; cvt.u32.u64 %0, t; }" : "=r"(a) : "l"(p));
    return a;
}
__device__ __forceinline__ uint32_t pack_h2(float a, float b) {
    __half2 h = __floats2half2_rn(a, b);
    return *(uint32_t*)&h;
}
// swizzled byte offset inside a [rows][64 halfs = 128B] tile (16B-group XOR row&7)
__device__ __forceinline__ uint32_t swb(int row, int k) {
    return (uint32_t)(row * 128 + (((k >> 3) ^ (row & 7)) << 4) + (k & 7) * 2);
}
// swizzled byte offset inside a [rows][128 halfs = 256B] tile
__device__ __forceinline__ uint32_t swb256(int row, int k) {
    return (uint32_t)(row * 256 + (((k >> 3) ^ (row & 7)) << 4) + (k & 7) * 2);
}
__device__ __forceinline__ uint32_t lds_h2(const char* base, int row, int k) {
    return *(const uint32_t*)(base + swb(row, k));
}
__device__ __forceinline__ void mma16(float* c, uint32_t a0, uint32_t a1, uint32_t a2,
                                      uint32_t a3, uint32_t b0, uint32_t b1) {
    asm volatile(
        "mma.sync.aligned.m16n8k16.row.col.f32.f16.f16.f32 "
        "{%0,%1,%2,%3}, {%4,%5,%6,%7}, {%8,%9}, {%0,%1,%2,%3};"
        : "+f"(c[0]), "+f"(c[1]), "+f"(c[2]), "+f"(c[3])
        : "r"(a0), "r"(a1), "r"(a2), "r"(a3), "r"(b0), "r"(b1));
}

// ---------------- fp32 -> fp16 conversion (8 elems/thread, uint4 store) ----------------
__global__ void f2h_kernel(const float* __restrict__ X, __half* __restrict__ Y, int n8)
{
    const int i = blockIdx.x * blockDim.x + threadIdx.x;
    if (i >= n8) return;
    float4 a = ((const float4*)X)[2 * i];
    float4 b = ((const float4*)X)[2 * i + 1];
    uint4 o = make_uint4(pack_h2(a.x, a.y), pack_h2(a.z, a.w),
                         pack_h2(b.x, b.y), pack_h2(b.z, b.w));
    ((uint4*)Y)[i] = o;
}

// ======================= fp16 mma.sync GEMM =======================
// C[M,N] = A[M,K] @ B[N,K]^T + T[M,16] @ Bl[N,16]^T (+ Res)
__global__ __launch_bounds__(256, 2) void gemm_fp16(
    const __half* __restrict__ A, const __half* __restrict__ B,
    const float* __restrict__ T, const float* __restrict__ Bl,
    const float* __restrict__ Res, float* __restrict__ C,
    int M, int N, int K)
{
    extern __shared__ char smc[];
    const uint32_t sbase = smem_u32(smc);
    const int tid = threadIdx.x;
    const int wid = tid >> 5, lane = tid & 31;
    const int gid = lane >> 2, tig = lane & 3;
    const int wm = wid >> 2, wn = wid & 3;          // warp grid 2 x 4
    const int m0 = blockIdx.x << 7, n0 = blockIdx.y << 7;

    const int KT = K >> 6;        // 64-wide K tiles
    const int TT = KT + 1;        // + LoRA tile

    float acc[4][4][4];
    #pragma unroll
    for (int i = 0; i < 4; i++)
        #pragma unroll
        for (int j = 0; j < 4; j++)
            #pragma unroll
            for (int c = 0; c < 4; c++) acc[i][j][c] = 0.f;

    const __half* Ag = A + (size_t)m0 * K;
    const __half* Bg = B + (size_t)n0 * K;

    #define CP_TILE(t, b)                                                            \
    do {                                                                             \
        const int k0 = (t) << 6;                                                     \
        const uint32_t ab = sbase + (uint32_t)(b) * 32768u;                          \
        const uint32_t bb = ab + 16384u;                                             \
        _Pragma("unroll")                                                            \
        for (int it = 0; it < 4; it++) {                                             \
            const int li = it * 256 + tid;                                           \
            const int row = li >> 3, g = li & 7;                                     \
            const uint32_t off = (uint32_t)(row * 128 + ((g ^ (row & 7)) << 4));     \
            const __half* sa = Ag + (size_t)row * K + k0 + g * 8;                    \
            const __half* sb = Bg + (size_t)row * K + k0 + g * 8;                    \
            asm volatile("cp.async.cg.shared.global [%0], [%1], 16;"                 \
                         :: "r"(ab + off), "l"(sa));                                 \
            asm volatile("cp.async.cg.shared.global [%0], [%1], 16;"                 \
                         :: "r"(bb + off), "l"(sb));                                 \
        }                                                                            \
        asm volatile("cp.async.commit_group;");                                      \
    } while (0)

    #define LORA_TILE(b)                                                             \
    do {                                                                             \
        char* ap = smc + (b) * 32768;                                                \
        char* bp = ap + 16384;                                                       \
        _Pragma("unroll")                                                            \
        for (int it = 0; it < 4; it++) {                                             \
            const int li = it * 256 + tid;                                           \
            const int row = li >> 3, g = li & 7;                                     \
            const uint32_t off = (uint32_t)(row * 128 + ((g ^ (row & 7)) << 4));     \
            uint4 ua = make_uint4(0, 0, 0, 0);                                       \
            uint4 ub = make_uint4(0, 0, 0, 0);                                       \
            if (g < 2) {                                                             \
                const float* ts = T  + (size_t)(m0 + row) * RLORA + g * 8;           \
                const float* bs = Bl + (size_t)(n0 + row) * RLORA + g * 8;           \
                float4 t0 = *(const float4*)ts;                                      \
                float4 t1 = *(const float4*)(ts + 4);                                \
                float4 b0 = *(const float4*)bs;                                      \
                float4 b1 = *(const float4*)(bs + 4);                                \
                ua = make_uint4(pack_h2(t0.x, t0.y), pack_h2(t0.z, t0.w),            \
                                pack_h2(t1.x, t1.y), pack_h2(t1.z, t1.w));           \
                ub = make_uint4(pack_h2(b0.x, b0.y), pack_h2(b0.z, b0.w),            \
                                pack_h2(b1.x, b1.y), pack_h2(b1.z, b1.w));           \
            }                                                                        \
            *(uint4*)(ap + off) = ua;                                                \
            *(uint4*)(bp + off) = ub;                                                \
        }                                                                            \
    } while (0)

    CP_TILE(0, 0);

    for (int t = 0; t < TT; t++) {
        if (t + 1 < TT) {
            if (t + 1 < KT) CP_TILE(t + 1, (t + 1) & 1);
            else            LORA_TILE((t + 1) & 1);
        }
        if (t + 1 < KT) asm volatile("cp.async.wait_group 1;" ::: "memory");
        else            asm volatile("cp.async.wait_group 0;" ::: "memory");
        __syncthreads();

        const char* As = smc + (t & 1) * 32768;
        const char* Bs = As + 16384;

        #pragma unroll
        for (int s = 0; s < 4; s++) {
            const int kb = s * 16;
            uint32_t af[4][4], bf[4][2];
            #pragma unroll
            for (int mi = 0; mi < 4; mi++) {
                const int r0 = wm * 64 + mi * 16 + gid;
                af[mi][0] = lds_h2(As, r0,     kb + 2 * tig);
                af[mi][1] = lds_h2(As, r0 + 8, kb + 2 * tig);
                af[mi][2] = lds_h2(As, r0,     kb + 8 + 2 * tig);
                af[mi][3] = lds_h2(As, r0 + 8, kb + 8 + 2 * tig);
            }
            #pragma unroll
            for (int nj = 0; nj < 4; nj++) {
                const int nr = wn * 32 + nj * 8 + gid;
                bf[nj][0] = lds_h2(Bs, nr, kb + 2 * tig);
                bf[nj][1] = lds_h2(Bs, nr, kb + 8 + 2 * tig);
            }
            #pragma unroll
            for (int mi = 0; mi < 4; mi++)
                #pragma unroll
                for (int nj = 0; nj < 4; nj++)
                    mma16(acc[mi][nj], af[mi][0], af[mi][1], af[mi][2], af[mi][3],
                          bf[nj][0], bf[nj][1]);
        }
        __syncthreads();
    }

    #pragma unroll
    for (int mi = 0; mi < 4; mi++) {
        const int gr0 = m0 + wm * 64 + mi * 16 + gid;
        #pragma unroll
        for (int nj = 0; nj < 4; nj++) {
            const int gc = n0 + wn * 32 + nj * 8 + tig * 2;
            const size_t i0 = (size_t)gr0 * N + gc;
            const size_t i1 = (size_t)(gr0 + 8) * N + gc;
            float2 o0 = {acc[mi][nj][0], acc[mi][nj][1]};
            float2 o1 = {acc[mi][nj][2], acc[mi][nj][3]};
            if (Res) {
                float2 r0 = *(const float2*)(Res + i0);
                float2 r1 = *(const float2*)(Res + i1);
                o0.x += r0.x; o0.y += r0.y;
                o1.x += r1.x; o1.y += r1.y;
            }
            *(float2*)(C + i0) = o0;
            *(float2*)(C + i1) = o1;
        }
    }
}

// ---------------- rmsnorm: one block per row (writes fp32 + fp16) ----------------
__global__ void rmsnorm_kernel(const float* __restrict__ X, const float* __restrict__ W,
                               float* __restrict__ Y, __half* __restrict__ Yh, int D)
{
    const int m = blockIdx.x, tid = threadIdx.x;   // 256 threads
    const float* x = X + (size_t)m * D;
    float s = 0.f;
    for (int k = tid * 4; k < D; k += 1024) {
        float4 v = *(const float4*)(x + k);
        s += v.x * v.x + v.y * v.y + v.z * v.z + v.w * v.w;
    }
    __shared__ float red[9];
    #pragma unroll
    for (int off = 16; off > 0; off >>= 1) s += __shfl_xor_sync(0xffffffffu, s, off);
    if ((tid & 31) == 0) red[tid >> 5] = s;
    __syncthreads();
    if (tid == 0) {
        float t = 0.f;
        #pragma unroll
        for (int i = 0; i < 8; i++) t += red[i];
        red[8] = rsqrtf(t / (float)D + 1e-5f);
    }
    __syncthreads();
    const float inv = red[8];
    float* y = Y + (size_t)m * D;
    __half* yh = Yh + (size_t)m * D;
    for (int k = tid * 4; k < D; k += 1024) {
        float4 v = *(const float4*)(x + k);
        float4 w = *(const float4*)(W + k);
        v.x = v.x * inv * w.x;
        v.y = v.y * inv * w.y;
        v.z = v.z * inv * w.z;
        v.w = v.w * inv * w.w;
        *(float4*)(y + k) = v;
        uint2 hp = make_uint2(pack_h2(v.x, v.y), pack_h2(v.z, v.w));
        *(uint2*)(yh + k) = hp;
    }
}

// ---------------- LoRA down-projection: T[M,16] = LSCALE * X[M,K] @ A[16,K]^T ----------------
__global__ void lora_tmp_kernel(const float* __restrict__ X, const float* __restrict__ Aw,
                                float* __restrict__ T, int K)
{
    const int m = blockIdx.x;
    const int w = threadIdx.x >> 5, lane = threadIdx.x & 31;
    const float* x = X + (size_t)m * K;
    const float* a = Aw + (size_t)w * K;
    float s = 0.f;
    for (int k = lane * 4; k < K; k += 128) {
        float4 xv = *(const float4*)(x + k);
        float4 av = *(const float4*)(a + k);
        s += xv.x * av.x + xv.y * av.y + xv.z * av.z + xv.w * av.w;
    }
    #pragma unroll
    for (int off = 16; off > 0; off >>= 1) s += __shfl_xor_sync(0xffffffffu, s, off);
    if (lane == 0) T[m * RLORA + w] = s * LSCALE;
}

// ---------------- RoPE (interleaved pairs), in place ----------------
__global__ void rope_kernel(float* __restrict__ X, const float* __restrict__ Cc,
                            const float* __restrict__ Sn, int H, int total)
{
    const int idx = blockIdx.x * blockDim.x + threadIdx.x;
    if (idx >= total) return;
    const int i = idx & 63;
    const int rest = idx >> 6;
    const int h = rest % H;
    const int s = rest / H;
    const float c = Cc[s * 64 + i], sn = Sn[s * 64 + i];
    float* p = X + (size_t)s * (H * 128) + h * 128 + 2 * i;
    const float x1 = p[0], x2 = p[1];
    p[0] = x1 * c - x2 * sn;
    p[1] = x1 * sn + x2 * c;
}

// ======================= fp16 flash attention (FA2, mma.sync) =======================
// 128 q-rows x one head per CTA. 8 warps, each owns a 16-row stripe (full N=64).
// Q,K,V read fp32, converted to fp16 smem. S/O accum fp32; P stays in registers.
// smem: Qs 128x256B (32K) + Ks 64x256B (16K) + Vs^T 128x128B (16K) = 64KB.
#define FLASH_SMEM 65536
__global__ __launch_bounds__(256, 1) void flash16_kernel(
    const float* __restrict__ Q, const float* __restrict__ Kf,
    const float* __restrict__ Vf, float* __restrict__ O, __half* __restrict__ Oh)
{
    extern __shared__ char smc[];
    char* Qs = smc;
    char* Ks = smc + 32768;
    char* Vs = smc + 49152;

    const int qb = gridDim.x - 1 - blockIdx.x;   // heaviest blocks first
    const int head = blockIdx.y;
    const int kvh = head >> 2;
    const int tid = threadIdx.x;
    const int wid = tid >> 5, lane = tid & 31;
    const int gid = lane >> 2, tig = lane & 3;
    const int qr0 = qb * 128;
    const float scale = 0.088388347648318447f;   // 1/sqrt(128)

    // load Q (pre-scaled) -> fp16 smem
    const float* Qg = Q + (size_t)qr0 * DM + head * 128;
    for (int li = tid; li < 4096; li += 256) {
        const int r = li >> 5, c4 = li & 31;
        float4 v = *(const float4*)(Qg + (size_t)r * DM + c4 * 4);
        uint2 hp = make_uint2(pack_h2(v.x * scale, v.y * scale),
                              pack_h2(v.z * scale, v.w * scale));
        *(uint2*)(Qs + swb256(r, c4 * 4)) = hp;
    }

    float m_i[2] = {-1e30f, -1e30f}, l_i[2] = {0.f, 0.f};
    float oacc[16][4];
    #pragma unroll
    for (int i = 0; i < 16; i++) {
        oacc[i][0] = oacc[i][1] = oacc[i][2] = oacc[i][3] = 0.f;
    }

    const int r0 = qr0 + wid * 16 + gid;   // thread's row A
    const int r1 = r0 + 8;                  // row B
    const int ntiles = 2 * qb + 2;

    for (int kb = 0; kb < ntiles; kb++) {
        __syncthreads();
        // K tile 64x128 fp32 -> fp16 (rows = kcol, k-contig = headdim)
        const float* Kg = Kf + (size_t)(kb * 64) * KVDIM + kvh * 128;
        for (int li = tid; li < 2048; li += 256) {
            const int r = li >> 5, c4 = li & 31;
            float4 v = *(const float4*)(Kg + (size_t)r * KVDIM + c4 * 4);
            uint2 hp = make_uint2(pack_h2(v.x, v.y), pack_h2(v.z, v.w));
            *(uint2*)(Ks + swb256(r, c4 * 4)) = hp;
        }
        // V tile 64x128 -> transposed Vs[headdim][kcol], k-pairs packed per word
        const float* Vg = Vf + (size_t)(kb * 64) * KVDIM + kvh * 128;
        for (int li = tid; li < 1024; li += 256) {
            const int kp = li >> 5, c4 = li & 31;
            const int k0 = kp * 2, n0 = c4 * 4;
            float4 v0 = *(const float4*)(Vg + (size_t)k0 * KVDIM + n0);
            float4 v1 = *(const float4*)(Vg + (size_t)(k0 + 1) * KVDIM + n0);
            *(uint32_t*)(Vs + swb(n0 + 0, k0)) = pack_h2(v0.x, v1.x);
            *(uint32_t*)(Vs + swb(n0 + 1, k0)) = pack_h2(v0.y, v1.y);
            *(uint32_t*)(Vs + swb(n0 + 2, k0)) = pack_h2(v0.z, v1.z);
            *(uint32_t*)(Vs + swb(n0 + 3, k0)) = pack_h2(v0.w, v1.w);
        }
        __syncthreads();

        // S = Q K^T : 16 rows x 64 cols per warp
        float sfr[8][4];
        #pragma unroll
        for (int j = 0; j < 8; j++) sfr[j][0] = sfr[j][1] = sfr[j][2] = sfr[j][3] = 0.f;
        #pragma unroll
        for (int s = 0; s < 8; s++) {
            const int kd = s * 16;
            const int qa = wid * 16 + gid;
            uint32_t a0 = *(const uint32_t*)(Qs + swb256(qa,     kd + 2 * tig));
            uint32_t a1 = *(const uint32_t*)(Qs + swb256(qa + 8, kd + 2 * tig));
            uint32_t a2 = *(const uint32_t*)(Qs + swb256(qa,     kd + 8 + 2 * tig));
            uint32_t a3 = *(const uint32_t*)(Qs + swb256(qa + 8, kd + 8 + 2 * tig));
            #pragma unroll
            for (int nj = 0; nj < 8; nj++) {
                uint32_t b0 = *(const uint32_t*)(Ks + swb256(nj * 8 + gid, kd + 2 * tig));
                uint32_t b1 = *(const uint32_t*)(Ks + swb256(nj * 8 + gid, kd + 8 + 2 * tig));
                mma16(sfr[nj], a0, a1, a2, a3, b0, b1);
            }
        }
        // causal mask (only tiles touching the diagonal)
        if (kb * 64 + 63 > r0) {
            #pragma unroll
            for (int nj = 0; nj < 8; nj++) {
                const int c0 = kb * 64 + nj * 8 + 2 * tig, c1 = c0 + 1;
                if (c0 > r0) sfr[nj][0] = -1e30f;
                if (c1 > r0) sfr[nj][1] = -1e30f;
                if (c0 > r1) sfr[nj][2] = -1e30f;
                if (c1 > r1) sfr[nj][3] = -1e30f;
            }
        }
        // online softmax for the thread's two rows
        uint32_t ph[8][2];
        {
            float mx0 = -1e30f, mx1 = -1e30f;
            #pragma unroll
            for (int nj = 0; nj < 8; nj++) {
                mx0 = fmaxf(mx0, fmaxf(sfr[nj][0], sfr[nj][1]));
                mx1 = fmaxf(mx1, fmaxf(sfr[nj][2], sfr[nj][3]));
            }
            mx0 = fmaxf(mx0, __shfl_xor_sync(0xffffffffu, mx0, 1));
            mx0 = fmaxf(mx0, __shfl_xor_sync(0xffffffffu, mx0, 2));
            mx1 = fmaxf(mx1, __shfl_xor_sync(0xffffffffu, mx1, 1));
            mx1 = fmaxf(mx1, __shfl_xor_sync(0xffffffffu, mx1, 2));
            const float mn0 = fmaxf(m_i[0], mx0), mn1 = fmaxf(m_i[1], mx1);
            const float al0 = __expf(m_i[0] - mn0), al1 = __expf(m_i[1] - mn1);
            float rs0 = 0.f, rs1 = 0.f;
            #pragma unroll
            for (int nj = 0; nj < 8; nj++) {
                float p0 = __expf(sfr[nj][0] - mn0);
                float p1 = __expf(sfr[nj][1] - mn0);
                float p2 = __expf(sfr[nj][2] - mn1);
                float p3 = __expf(sfr[nj][3] - mn1);
                rs0 += p0 + p1; rs1 += p2 + p3;
                ph[nj][0] = pack_h2(p0, p1);
                ph[nj][1] = pack_h2(p2, p3);
            }
            rs0 += __shfl_xor_sync(0xffffffffu, rs0, 1);
            rs0 += __shfl_xor_sync(0xffffffffu, rs0, 2);
            rs1 += __shfl_xor_sync(0xffffffffu, rs1, 1);
            rs1 += __shfl_xor_sync(0xffffffffu, rs1, 2);
            m_i[0] = mn0; m_i[1] = mn1;
            l_i[0] = l_i[0] * al0 + rs0;
            l_i[1] = l_i[1] * al1 + rs1;
            #pragma unroll
            for (int nf = 0; nf < 16; nf++) {
                oacc[nf][0] *= al0; oacc[nf][1] *= al0;
                oacc[nf][2] *= al1; oacc[nf][3] *= al1;
            }
        }
        // O += P V  (P fragments reused directly from S fragments)
        #pragma unroll
        for (int kk = 0; kk < 4; kk++) {
            const uint32_t a0 = ph[2 * kk][0], a1 = ph[2 * kk][1];
            const uint32_t a2 = ph[2 * kk + 1][0], a3 = ph[2 * kk + 1][1];
            #pragma unroll
            for (int nf = 0; nf < 16; nf++) {
                uint32_t b0 = *(const uint32_t*)(Vs + swb(nf * 8 + gid, kk * 16 + 2 * tig));
                uint32_t b1 = *(const uint32_t*)(Vs + swb(nf * 8 + gid, kk * 16 + 8 + 2 * tig));
                mma16(oacc[nf], a0, a1, a2, a3, b0, b1);
            }
        }
    }

    // epilogue: normalize, write fp32 + fp16
    const float inv0 = 1.f / l_i[0], inv1 = 1.f / l_i[1];
    #pragma unroll
    for (int nf = 0; nf < 16; nf++) {
        const int gc = head * 128 + nf * 8 + 2 * tig;
        const size_t i0 = (size_t)r0 * DM + gc;
        const size_t i1 = (size_t)r1 * DM + gc;
        float2 o0 = {oacc[nf][0] * inv0, oacc[nf][1] * inv0};
        float2 o1 = {oacc[nf][2] * inv1, oacc[nf][3] * inv1};
        *(float2*)(O + i0) = o0;
        *(float2*)(O + i1) = o1;
        *(uint32_t*)(Oh + i0) = pack_h2(o0.x, o0.y);
        *(uint32_t*)(Oh + i1) = pack_h2(o1.x, o1.y);
    }
}

// ---------------- SwiGLU: G = silu(G) * U (fp32 in place + fp16 mirror) ----------------
__global__ void silu_mul_kernel(float* __restrict__ G, const float* __restrict__ U,
                                __half* __restrict__ Gh, int n4)
{
    const int i = blockIdx.x * blockDim.x + threadIdx.x;
    if (i >= n4) return;
    float4 g = ((const float4*)G)[i];
    float4 u = ((const float4*)U)[i];
    g.x = g.x / (1.f + __expf(-g.x)) * u.x;
    g.y = g.y / (1.f + __expf(-g.y)) * u.y;
    g.z = g.z / (1.f + __expf(-g.z)) * u.z;
    g.w = g.w / (1.f + __expf(-g.w)) * u.w;
    ((float4*)G)[i] = g;
    uint2 hp = make_uint2(pack_h2(g.x, g.y), pack_h2(g.z, g.w));
    ((uint2*)Gh)[i] = hp;
}

// ---------------- launcher ----------------
#define GEMM_SMEM 65536

extern "C" void kernel_launch(void* const* d_in, const int* in_sizes, int n_in,
                              void* d_out, int out_size)
{
    const float* data      = (const float*)d_in[0];
    const float* cosp      = (const float*)d_in[2];
    const float* sinp      = (const float*)d_in[3];
    const float* attn_norm = (const float*)d_in[4];
    const float* wq        = (const float*)d_in[5];
    const float* wk        = (const float*)d_in[6];
    const float* wv        = (const float*)d_in[7];
    const float* wo        = (const float*)d_in[8];
    const float* wq_a      = (const float*)d_in[9];
    const float* wq_b      = (const float*)d_in[10];
    const float* wk_a      = (const float*)d_in[11];
    const float* wk_b      = (const float*)d_in[12];
    const float* wv_a      = (const float*)d_in[13];
    const float* wv_b      = (const float*)d_in[14];
    const float* wo_a      = (const float*)d_in[15];
    const float* wo_b      = (const float*)d_in[16];
    const float* ffn_norm  = (const float*)d_in[17];
    const float* w1        = (const float*)d_in[18];
    const float* w2        = (const float*)d_in[19];
    const float* w3        = (const float*)d_in[20];
    const float* w1_a      = (const float*)d_in[21];
    const float* w1_b      = (const float*)d_in[22];
    const float* w2_a      = (const float*)d_in[23];
    const float* w2_b      = (const float*)d_in[24];
    const float* w3_a      = (const float*)d_in[25];
    const float* w3_b      = (const float*)d_in[26];
    float* out = (float*)d_out;

    float *h, *q, *k, *v, *attn, *res2, *gate, *up, *tmp;
    cudaGetSymbolAddress((void**)&h, g_h);
    cudaGetSymbolAddress((void**)&q, g_q);
    cudaGetSymbolAddress((void**)&k, g_k);
    cudaGetSymbolAddress((void**)&v, g_v);
    cudaGetSymbolAddress((void**)&attn, g_attn);
    cudaGetSymbolAddress((void**)&res2, g_res2);
    cudaGetSymbolAddress((void**)&gate, g_gate);
    cudaGetSymbolAddress((void**)&up, g_up);
    cudaGetSymbolAddress((void**)&tmp, g_tmp);

    __half *wq_h, *wk_h, *wv_h, *wo_h, *w1_h, *w3_h, *w2_h, *h_h, *attn_h, *gu_h;
    cudaGetSymbolAddress((void**)&wq_h, g_wq_h);
    cudaGetSymbolAddress((void**)&wk_h, g_wk_h);
    cudaGetSymbolAddress((void**)&wv_h, g_wv_h);
    cudaGetSymbolAddress((void**)&wo_h, g_wo_h);
    cudaGetSymbolAddress((void**)&w1_h, g_w1_h);
    cudaGetSymbolAddress((void**)&w3_h, g_w3_h);
    cudaGetSymbolAddress((void**)&w2_h, g_w2_h);
    cudaGetSymbolAddress((void**)&h_h, g_h_h);
    cudaGetSymbolAddress((void**)&attn_h, g_attn_h);
    cudaGetSymbolAddress((void**)&gu_h, g_gu_h);

    cudaFuncSetAttribute(flash16_kernel, cudaFuncAttributeMaxDynamicSharedMemorySize, FLASH_SMEM);
    cudaFuncSetAttribute(gemm_fp16, cudaFuncAttributeMaxDynamicSharedMemorySize, GEMM_SMEM);

    // ---- weight conversions (fp32 -> fp16) ----
    f2h_kernel<<<(DM * DM / 8) / 256, 256>>>(wq, wq_h, DM * DM / 8);
    f2h_kernel<<<(KVDIM * DM / 8) / 256, 256>>>(wk, wk_h, KVDIM * DM / 8);
    f2h_kernel<<<(KVDIM * DM / 8) / 256, 256>>>(wv, wv_h, KVDIM * DM / 8);
    f2h_kernel<<<(DM * DM / 8) / 256, 256>>>(wo, wo_h, DM * DM / 8);
    f2h_kernel<<<(FF * DM / 8) / 256, 256>>>(w1, w1_h, FF * DM / 8);
    f2h_kernel<<<(FF * DM / 8) / 256, 256>>>(w3, w3_h, FF * DM / 8);
    f2h_kernel<<<(DM * FF / 8) / 256, 256>>>(w2, w2_h, DM * FF / 8);

    // ---- attention block ----
    rmsnorm_kernel<<<SLEN, 256>>>(data, attn_norm, h, h_h, DM);

    lora_tmp_kernel<<<SLEN, 512>>>(h, wq_a, tmp, DM);
    gemm_fp16<<<dim3(SLEN / 128, DM / 128), 256, GEMM_SMEM>>>(h_h, wq_h, tmp, wq_b, nullptr, q, SLEN, DM, DM);
    rope_kernel<<<(SLEN * 32 * 64) / 256, 256>>>(q, cosp, sinp, 32, SLEN * 32 * 64);

    lora_tmp_kernel<<<SLEN, 512>>>(h, wk_a, tmp, DM);
    gemm_fp16<<<dim3(SLEN / 128, KVDIM / 128), 256, GEMM_SMEM>>>(h_h, wk_h, tmp, wk_b, nullptr, k, SLEN, KVDIM, DM);
    rope_kernel<<<(SLEN * 8 * 64) / 256, 256>>>(k, cosp, sinp, 8, SLEN * 8 * 64);

    lora_tmp_kernel<<<SLEN, 512>>>(h, wv_a, tmp, DM);
    gemm_fp16<<<dim3(SLEN / 128, KVDIM / 128), 256, GEMM_SMEM>>>(h_h, wv_h, tmp, wv_b, nullptr, v, SLEN, KVDIM, DM);

    flash16_kernel<<<dim3(SLEN / 128, 32), 256, FLASH_SMEM>>>(q, k, v, attn, attn_h);

    lora_tmp_kernel<<<SLEN, 512>>>(attn, wo_a, tmp, DM);
    gemm_fp16<<<dim3(SLEN / 128, DM / 128), 256, GEMM_SMEM>>>(attn_h, wo_h, tmp, wo_b, data, res2, SLEN, DM, DM);

    // ---- FFN block ----
    rmsnorm_kernel<<<SLEN, 256>>>(res2, ffn_norm, h, h_h, DM);

    lora_tmp_kernel<<<SLEN, 512>>>(h, w1_a, tmp, DM);
    gemm_fp16<<<dim3(SLEN / 128, FF / 128), 256, GEMM_SMEM>>>(h_h, w1_h, tmp, w1_b, nullptr, gate, SLEN, FF, DM);

    lora_tmp_kernel<<<SLEN, 512>>>(h, w3_a, tmp, DM);
    gemm_fp16<<<dim3(SLEN / 128, FF / 128), 256, GEMM_SMEM>>>(h_h, w3_h, tmp, w3_b, nullptr, up, SLEN, FF, DM);

    silu_mul_kernel<<<(SLEN * FF / 4) / 256, 256>>>(gate, up, gu_h, SLEN * FF / 4);

    lora_tmp_kernel<<<SLEN, 512>>>(gate, w2_a, tmp, FF);
    gemm_fp16<<<dim3(SLEN / 128, DM / 128), 256, GEMM_SMEM>>>(gu_h, w2_h, tmp, w2_b, res2, out, SLEN, DM, FF);
}

// round 14
// speedup vs baseline: 1.4729x; 1.4729x over previous
#include <cuda_runtime.h>
#include <cuda_fp16.h>
#include <cstdint>

#define SLEN  1024
#define DM    4096
#define FF    14336
#define KVDIM 1024
#define RLORA 16
#define LSCALE 2.0f

// ---------------- scratch (device globals; no allocations) ----------------
__device__ float g_h[SLEN * DM];
__device__ float g_q[SLEN * DM];
__device__ float g_k[SLEN * KVDIM];
__device__ float g_v[SLEN * KVDIM];
__device__ float g_attn[SLEN * DM];
__device__ float g_res2[SLEN * DM];
__device__ float g_gate[SLEN * FF];
__device__ float g_up[SLEN * FF];
__device__ float g_tmp[SLEN * RLORA];

// fp16 mirrors
__device__ __half g_wq_h[DM * DM];
__device__ __half g_wk_h[KVDIM * DM];
__device__ __half g_wv_h[KVDIM * DM];
__device__ __half g_wo_h[DM * DM];
__device__ __half g_w1_h[FF * DM];
__device__ __half g_w3_h[FF * DM];
__device__ __half g_w2_h[DM * FF];
__device__ __half g_h_h[SLEN * DM];
__device__ __half g_attn_h[SLEN * DM];
__device__ __half g_gu_h[SLEN * FF];

// ======================= helpers =======================
__device__ __forceinline__ uint32_t smem_u32(const void* p) {
    uint32_t a;
    asm("{ .reg .u64 t; cvta.to.shared.u64 t, %1; cvt.u32.u64 %0, t; }" : "=r"(a) : "l"(p));
    return a;
}
__device__ __forceinline__ uint32_t pack_h2(float a, float b) {
    __half2 h = __floats2half2_rn(a, b);
    return *(uint32_t*)&h;
}
// swizzled byte offset inside a [rows][64 halfs = 128B] tile (16B-group XOR row&7)
__device__ __forceinline__ uint32_t swb(int row, int k) {
    return (uint32_t)(row * 128 + (((k >> 3) ^ (row & 7)) << 4) + (k & 7) * 2);
}
// swizzled byte offset inside a [rows][128 halfs = 256B] tile
__device__ __forceinline__ uint32_t swb256(int row, int k) {
    return (uint32_t)(row * 256 + (((k >> 3) ^ (row & 7)) << 4) + (k & 7) * 2);
}
__device__ __forceinline__ uint32_t lds_h2(const char* base, int row, int k) {
    return *(const uint32_t*)(base + swb(row, k));
}
__device__ __forceinline__ void mma16(float* c, uint32_t a0, uint32_t a1, uint32_t a2,
                                      uint32_t a3, uint32_t b0, uint32_t b1) {
    asm volatile(
        "mma.sync.aligned.m16n8k16.row.col.f32.f16.f16.f32 "
        "{%0,%1,%2,%3}, {%4,%5,%6,%7}, {%8,%9}, {%0,%1,%2,%3};"
        : "+f"(c[0]), "+f"(c[1]), "+f"(c[2]), "+f"(c[3])
        : "r"(a0), "r"(a1), "r"(a2), "r"(a3), "r"(b0), "r"(b1));
}
__device__ __forceinline__ void ldm_x4(uint32_t* r, uint32_t addr) {
    asm volatile("ldmatrix.sync.aligned.m8n8.x4.shared.b16 {%0,%1,%2,%3}, [%4];"
                 : "=r"(r[0]), "=r"(r[1]), "=r"(r[2]), "=r"(r[3]) : "r"(addr));
}
__device__ __forceinline__ void ldm_x4_t(uint32_t* r, uint32_t addr) {
    asm volatile("ldmatrix.sync.aligned.m8n8.x4.trans.shared.b16 {%0,%1,%2,%3}, [%4];"
                 : "=r"(r[0]), "=r"(r[1]), "=r"(r[2]), "=r"(r[3]) : "r"(addr));
}

// ---------------- fp32 -> fp16 conversion (8 elems/thread, uint4 store) ----------------
__global__ void f2h_kernel(const float* __restrict__ X, __half* __restrict__ Y, int n8)
{
    const int i = blockIdx.x * blockDim.x + threadIdx.x;
    if (i >= n8) return;
    float4 a = ((const float4*)X)[2 * i];
    float4 b = ((const float4*)X)[2 * i + 1];
    uint4 o = make_uint4(pack_h2(a.x, a.y), pack_h2(a.z, a.w),
                         pack_h2(b.x, b.y), pack_h2(b.z, b.w));
    ((uint4*)Y)[i] = o;
}

// ======================= fp16 mma.sync GEMM =======================
// C[M,N] = A[M,K] @ B[N,K]^T + T[M,16] @ Bl[N,16]^T (+ Res)
__global__ __launch_bounds__(256, 2) void gemm_fp16(
    const __half* __restrict__ A, const __half* __restrict__ B,
    const float* __restrict__ T, const float* __restrict__ Bl,
    const float* __restrict__ Res, float* __restrict__ C,
    int M, int N, int K)
{
    extern __shared__ char smc[];
    const uint32_t sbase = smem_u32(smc);
    const int tid = threadIdx.x;
    const int wid = tid >> 5, lane = tid & 31;
    const int gid = lane >> 2, tig = lane & 3;
    const int wm = wid >> 2, wn = wid & 3;          // warp grid 2 x 4
    const int m0 = blockIdx.x << 7, n0 = blockIdx.y << 7;

    const int KT = K >> 6;        // 64-wide K tiles
    const int TT = KT + 1;        // + LoRA tile

    float acc[4][4][4];
    #pragma unroll
    for (int i = 0; i < 4; i++)
        #pragma unroll
        for (int j = 0; j < 4; j++)
            #pragma unroll
            for (int c = 0; c < 4; c++) acc[i][j][c] = 0.f;

    const __half* Ag = A + (size_t)m0 * K;
    const __half* Bg = B + (size_t)n0 * K;

    #define CP_TILE(t, b)                                                            \
    do {                                                                             \
        const int k0 = (t) << 6;                                                     \
        const uint32_t ab = sbase + (uint32_t)(b) * 32768u;                          \
        const uint32_t bb = ab + 16384u;                                             \
        _Pragma("unroll")                                                            \
        for (int it = 0; it < 4; it++) {                                             \
            const int li = it * 256 + tid;                                           \
            const int row = li >> 3, g = li & 7;                                     \
            const uint32_t off = (uint32_t)(row * 128 + ((g ^ (row & 7)) << 4));     \
            const __half* sa = Ag + (size_t)row * K + k0 + g * 8;                    \
            const __half* sb = Bg + (size_t)row * K + k0 + g * 8;                    \
            asm volatile("cp.async.cg.shared.global [%0], [%1], 16;"                 \
                         :: "r"(ab + off), "l"(sa));                                 \
            asm volatile("cp.async.cg.shared.global [%0], [%1], 16;"                 \
                         :: "r"(bb + off), "l"(sb));                                 \
        }                                                                            \
        asm volatile("cp.async.commit_group;");                                      \
    } while (0)

    #define LORA_TILE(b)                                                             \
    do {                                                                             \
        char* ap = smc + (b) * 32768;                                                \
        char* bp = ap + 16384;                                                       \
        _Pragma("unroll")                                                            \
        for (int it = 0; it < 4; it++) {                                             \
            const int li = it * 256 + tid;                                           \
            const int row = li >> 3, g = li & 7;                                     \
            const uint32_t off = (uint32_t)(row * 128 + ((g ^ (row & 7)) << 4));     \
            uint4 ua = make_uint4(0, 0, 0, 0);                                       \
            uint4 ub = make_uint4(0, 0, 0, 0);                                       \
            if (g < 2) {                                                             \
                const float* ts = T  + (size_t)(m0 + row) * RLORA + g * 8;           \
                const float* bs = Bl + (size_t)(n0 + row) * RLORA + g * 8;           \
                float4 t0 = *(const float4*)ts;                                      \
                float4 t1 = *(const float4*)(ts + 4);                                \
                float4 b0 = *(const float4*)bs;                                      \
                float4 b1 = *(const float4*)(bs + 4);                                \
                ua = make_uint4(pack_h2(t0.x, t0.y), pack_h2(t0.z, t0.w),            \
                                pack_h2(t1.x, t1.y), pack_h2(t1.z, t1.w));           \
                ub = make_uint4(pack_h2(b0.x, b0.y), pack_h2(b0.z, b0.w),            \
                                pack_h2(b1.x, b1.y), pack_h2(b1.z, b1.w));           \
            }                                                                        \
            *(uint4*)(ap + off) = ua;                                                \
            *(uint4*)(bp + off) = ub;                                                \
        }                                                                            \
    } while (0)

    CP_TILE(0, 0);

    for (int t = 0; t < TT; t++) {
        if (t + 1 < TT) {
            if (t + 1 < KT) CP_TILE(t + 1, (t + 1) & 1);
            else            LORA_TILE((t + 1) & 1);
        }
        if (t + 1 < KT) asm volatile("cp.async.wait_group 1;" ::: "memory");
        else            asm volatile("cp.async.wait_group 0;" ::: "memory");
        __syncthreads();

        const char* As = smc + (t & 1) * 32768;
        const char* Bs = As + 16384;

        #pragma unroll
        for (int s = 0; s < 4; s++) {
            const int kb = s * 16;
            uint32_t af[4][4], bf[4][2];
            #pragma unroll
            for (int mi = 0; mi < 4; mi++) {
                const int r0 = wm * 64 + mi * 16 + gid;
                af[mi][0] = lds_h2(As, r0,     kb + 2 * tig);
                af[mi][1] = lds_h2(As, r0 + 8, kb + 2 * tig);
                af[mi][2] = lds_h2(As, r0,     kb + 8 + 2 * tig);
                af[mi][3] = lds_h2(As, r0 + 8, kb + 8 + 2 * tig);
            }
            #pragma unroll
            for (int nj = 0; nj < 4; nj++) {
                const int nr = wn * 32 + nj * 8 + gid;
                bf[nj][0] = lds_h2(Bs, nr, kb + 2 * tig);
                bf[nj][1] = lds_h2(Bs, nr, kb + 8 + 2 * tig);
            }
            #pragma unroll
            for (int mi = 0; mi < 4; mi++)
                #pragma unroll
                for (int nj = 0; nj < 4; nj++)
                    mma16(acc[mi][nj], af[mi][0], af[mi][1], af[mi][2], af[mi][3],
                          bf[nj][0], bf[nj][1]);
        }
        __syncthreads();
    }

    #pragma unroll
    for (int mi = 0; mi < 4; mi++) {
        const int gr0 = m0 + wm * 64 + mi * 16 + gid;
        #pragma unroll
        for (int nj = 0; nj < 4; nj++) {
            const int gc = n0 + wn * 32 + nj * 8 + tig * 2;
            const size_t i0 = (size_t)gr0 * N + gc;
            const size_t i1 = (size_t)(gr0 + 8) * N + gc;
            float2 o0 = {acc[mi][nj][0], acc[mi][nj][1]};
            float2 o1 = {acc[mi][nj][2], acc[mi][nj][3]};
            if (Res) {
                float2 r0 = *(const float2*)(Res + i0);
                float2 r1 = *(const float2*)(Res + i1);
                o0.x += r0.x; o0.y += r0.y;
                o1.x += r1.x; o1.y += r1.y;
            }
            *(float2*)(C + i0) = o0;
            *(float2*)(C + i1) = o1;
        }
    }
}

// ---------------- rmsnorm: one block per row (writes fp32 + fp16) ----------------
__global__ void rmsnorm_kernel(const float* __restrict__ X, const float* __restrict__ W,
                               float* __restrict__ Y, __half* __restrict__ Yh, int D)
{
    const int m = blockIdx.x, tid = threadIdx.x;   // 256 threads
    const float* x = X + (size_t)m * D;
    float s = 0.f;
    for (int k = tid * 4; k < D; k += 1024) {
        float4 v = *(const float4*)(x + k);
        s += v.x * v.x + v.y * v.y + v.z * v.z + v.w * v.w;
    }
    __shared__ float red[9];
    #pragma unroll
    for (int off = 16; off > 0; off >>= 1) s += __shfl_xor_sync(0xffffffffu, s, off);
    if ((tid & 31) == 0) red[tid >> 5] = s;
    __syncthreads();
    if (tid == 0) {
        float t = 0.f;
        #pragma unroll
        for (int i = 0; i < 8; i++) t += red[i];
        red[8] = rsqrtf(t / (float)D + 1e-5f);
    }
    __syncthreads();
    const float inv = red[8];
    float* y = Y + (size_t)m * D;
    __half* yh = Yh + (size_t)m * D;
    for (int k = tid * 4; k < D; k += 1024) {
        float4 v = *(const float4*)(x + k);
        float4 w = *(const float4*)(W + k);
        v.x = v.x * inv * w.x;
        v.y = v.y * inv * w.y;
        v.z = v.z * inv * w.z;
        v.w = v.w * inv * w.w;
        *(float4*)(y + k) = v;
        uint2 hp = make_uint2(pack_h2(v.x, v.y), pack_h2(v.z, v.w));
        *(uint2*)(yh + k) = hp;
    }
}

// ---------------- LoRA down-projection: T[M,16] = LSCALE * X[M,K] @ A[16,K]^T ----------------
__global__ void lora_tmp_kernel(const float* __restrict__ X, const float* __restrict__ Aw,
                                float* __restrict__ T, int K)
{
    const int m = blockIdx.x;
    const int w = threadIdx.x >> 5, lane = threadIdx.x & 31;
    const float* x = X + (size_t)m * K;
    const float* a = Aw + (size_t)w * K;
    float s = 0.f;
    for (int k = lane * 4; k < K; k += 128) {
        float4 xv = *(const float4*)(x + k);
        float4 av = *(const float4*)(a + k);
        s += xv.x * av.x + xv.y * av.y + xv.z * av.z + xv.w * av.w;
    }
    #pragma unroll
    for (int off = 16; off > 0; off >>= 1) s += __shfl_xor_sync(0xffffffffu, s, off);
    if (lane == 0) T[m * RLORA + w] = s * LSCALE;
}

// ---------------- RoPE (interleaved pairs), in place ----------------
__global__ void rope_kernel(float* __restrict__ X, const float* __restrict__ Cc,
                            const float* __restrict__ Sn, int H, int total)
{
    const int idx = blockIdx.x * blockDim.x + threadIdx.x;
    if (idx >= total) return;
    const int i = idx & 63;
    const int rest = idx >> 6;
    const int h = rest % H;
    const int s = rest / H;
    const float c = Cc[s * 64 + i], sn = Sn[s * 64 + i];
    float* p = X + (size_t)s * (H * 128) + h * 128 + 2 * i;
    const float x1 = p[0], x2 = p[1];
    p[0] = x1 * c - x2 * sn;
    p[1] = x1 * sn + x2 * c;
}

// ======================= fp16 flash attention v2 (FA2, ldmatrix) =======================
// 128 q-rows x one head per CTA. 8 warps, each owns a 16-row stripe (full N=64).
// Q fragments register-resident (loaded once via ldmatrix). K,V stored row-major
// fp16 smem (conflict-free uint2 stores); fragments via ldmatrix (V with .trans).
// smem: Qs 128x256B (32K) + Ks 64x256B (16K) + Vs 64x256B (16K) = 64KB.
#define FLASH_SMEM 65536
__global__ __launch_bounds__(256, 1) void flash16_kernel(
    const float* __restrict__ Q, const float* __restrict__ Kf,
    const float* __restrict__ Vf, float* __restrict__ O, __half* __restrict__ Oh)
{
    extern __shared__ char smc[];
    const uint32_t sQ = smem_u32(smc);
    const uint32_t sK = sQ + 32768u;
    const uint32_t sV = sQ + 49152u;
    char* Qs = smc;
    char* Ks = smc + 32768;
    char* Vs = smc + 49152;

    const int qb = gridDim.x - 1 - blockIdx.x;   // heaviest blocks first
    const int head = blockIdx.y;
    const int kvh = head >> 2;
    const int tid = threadIdx.x;
    const int wid = tid >> 5, lane = tid & 31;
    const int gid = lane >> 2, tig = lane & 3;
    const int qr0 = qb * 128;
    const float scale = 0.088388347648318447f;   // 1/sqrt(128)

    // load Q (pre-scaled) -> fp16 smem
    const float* Qg = Q + (size_t)qr0 * DM + head * 128;
    for (int li = tid; li < 4096; li += 256) {
        const int r = li >> 5, c4 = li & 31;
        float4 v = *(const float4*)(Qg + (size_t)r * DM + c4 * 4);
        uint2 hp = make_uint2(pack_h2(v.x * scale, v.y * scale),
                              pack_h2(v.z * scale, v.w * scale));
        *(uint2*)(Qs + swb256(r, c4 * 4)) = hp;
    }
    __syncthreads();

    // Q fragments -> registers (once)
    uint32_t qf[8][4];
    {
        const int wr = wid * 16;
        const int row = wr + ((lane >> 3) & 1) * 8 + (lane & 7);
        const int ch = ((lane >> 4) & 1) * 8;
        #pragma unroll
        for (int s = 0; s < 8; s++)
            ldm_x4(qf[s], sQ + swb256(row, s * 16 + ch));
    }

    float m_i[2] = {-1e30f, -1e30f}, l_i[2] = {0.f, 0.f};
    float oacc[16][4];
    #pragma unroll
    for (int i = 0; i < 16; i++)
        oacc[i][0] = oacc[i][1] = oacc[i][2] = oacc[i][3] = 0.f;

    const int r0 = qr0 + wid * 16 + gid;   // thread's row A
    const int r1 = r0 + 8;                  // row B
    const int ntiles = 2 * qb + 2;

    for (int kb = 0; kb < ntiles; kb++) {
        __syncthreads();
        // K, V tiles 64x128 fp32 -> fp16 row-major smem (conflict-free)
        const float* Kg = Kf + (size_t)(kb * 64) * KVDIM + kvh * 128;
        const float* Vg = Vf + (size_t)(kb * 64) * KVDIM + kvh * 128;
        for (int li = tid; li < 2048; li += 256) {
            const int r = li >> 5, c4 = li & 31;
            const uint32_t off = swb256(r, c4 * 4);
            float4 kv = *(const float4*)(Kg + (size_t)r * KVDIM + c4 * 4);
            *(uint2*)(Ks + off) = make_uint2(pack_h2(kv.x, kv.y), pack_h2(kv.z, kv.w));
            float4 vv = *(const float4*)(Vg + (size_t)r * KVDIM + c4 * 4);
            *(uint2*)(Vs + off) = make_uint2(pack_h2(vv.x, vv.y), pack_h2(vv.z, vv.w));
        }
        __syncthreads();

        // S = Q K^T : 16 rows x 64 cols per warp
        float sfr[8][4];
        #pragma unroll
        for (int j = 0; j < 8; j++) sfr[j][0] = sfr[j][1] = sfr[j][2] = sfr[j][3] = 0.f;
        {
            const int krow7 = lane & 7;
            const int ksel = ((lane >> 4) & 1) * 8;   // nj vs nj+1
            const int csel = ((lane >> 3) & 1) * 8;   // kd vs kd+8
            #pragma unroll
            for (int s = 0; s < 8; s++) {
                const int kd = s * 16;
                #pragma unroll
                for (int njp = 0; njp < 4; njp++) {
                    uint32_t bf[4];
                    ldm_x4(bf, sK + swb256(njp * 16 + ksel + krow7, kd + csel));
                    mma16(sfr[2 * njp],     qf[s][0], qf[s][1], qf[s][2], qf[s][3], bf[0], bf[1]);
                    mma16(sfr[2 * njp + 1], qf[s][0], qf[s][1], qf[s][2], qf[s][3], bf[2], bf[3]);
                }
            }
        }
        // causal mask (only tiles touching the diagonal)
        if (kb * 64 + 63 > r0) {
            #pragma unroll
            for (int nj = 0; nj < 8; nj++) {
                const int c0 = kb * 64 + nj * 8 + 2 * tig, c1 = c0 + 1;
                if (c0 > r0) sfr[nj][0] = -1e30f;
                if (c1 > r0) sfr[nj][1] = -1e30f;
                if (c0 > r1) sfr[nj][2] = -1e30f;
                if (c1 > r1) sfr[nj][3] = -1e30f;
            }
        }
        // online softmax for the thread's two rows
        uint32_t ph[8][2];
        {
            float mx0 = -1e30f, mx1 = -1e30f;
            #pragma unroll
            for (int nj = 0; nj < 8; nj++) {
                mx0 = fmaxf(mx0, fmaxf(sfr[nj][0], sfr[nj][1]));
                mx1 = fmaxf(mx1, fmaxf(sfr[nj][2], sfr[nj][3]));
            }
            mx0 = fmaxf(mx0, __shfl_xor_sync(0xffffffffu, mx0, 1));
            mx0 = fmaxf(mx0, __shfl_xor_sync(0xffffffffu, mx0, 2));
            mx1 = fmaxf(mx1, __shfl_xor_sync(0xffffffffu, mx1, 1));
            mx1 = fmaxf(mx1, __shfl_xor_sync(0xffffffffu, mx1, 2));
            const float mn0 = fmaxf(m_i[0], mx0), mn1 = fmaxf(m_i[1], mx1);
            const float al0 = __expf(m_i[0] - mn0), al1 = __expf(m_i[1] - mn1);
            float rs0 = 0.f, rs1 = 0.f;
            #pragma unroll
            for (int nj = 0; nj < 8; nj++) {
                float p0 = __expf(sfr[nj][0] - mn0);
                float p1 = __expf(sfr[nj][1] - mn0);
                float p2 = __expf(sfr[nj][2] - mn1);
                float p3 = __expf(sfr[nj][3] - mn1);
                rs0 += p0 + p1; rs1 += p2 + p3;
                ph[nj][0] = pack_h2(p0, p1);
                ph[nj][1] = pack_h2(p2, p3);
            }
            rs0 += __shfl_xor_sync(0xffffffffu, rs0, 1);
            rs0 += __shfl_xor_sync(0xffffffffu, rs0, 2);
            rs1 += __shfl_xor_sync(0xffffffffu, rs1, 1);
            rs1 += __shfl_xor_sync(0xffffffffu, rs1, 2);
            m_i[0] = mn0; m_i[1] = mn1;
            l_i[0] = l_i[0] * al0 + rs0;
            l_i[1] = l_i[1] * al1 + rs1;
            #pragma unroll
            for (int nf = 0; nf < 16; nf++) {
                oacc[nf][0] *= al0; oacc[nf][1] *= al0;
                oacc[nf][2] *= al1; oacc[nf][3] *= al1;
            }
        }
        // O += P V  (V fragments via ldmatrix.trans from row-major Vs)
        {
            const int vrow7 = lane & 7;
            const int vksel = ((lane >> 3) & 1) * 8;   // k low/high 8
            const int vnsel = ((lane >> 4) & 1) * 8;   // nf vs nf+1
            #pragma unroll
            for (int kk = 0; kk < 4; kk++) {
                const uint32_t a0 = ph[2 * kk][0], a1 = ph[2 * kk][1];
                const uint32_t a2 = ph[2 * kk + 1][0], a3 = ph[2 * kk + 1][1];
                #pragma unroll
                for (int nfp = 0; nfp < 8; nfp++) {
                    uint32_t vb[4];
                    ldm_x4_t(vb, sV + swb256(kk * 16 + vksel + vrow7, nfp * 16 + vnsel));
                    mma16(oacc[2 * nfp],     a0, a1, a2, a3, vb[0], vb[1]);
                    mma16(oacc[2 * nfp + 1], a0, a1, a2, a3, vb[2], vb[3]);
                }
            }
        }
    }

    // epilogue: normalize, write fp32 + fp16
    const float inv0 = 1.f / l_i[0], inv1 = 1.f / l_i[1];
    #pragma unroll
    for (int nf = 0; nf < 16; nf++) {
        const int gc = head * 128 + nf * 8 + 2 * tig;
        const size_t i0 = (size_t)r0 * DM + gc;
        const size_t i1 = (size_t)r1 * DM + gc;
        float2 o0 = {oacc[nf][0] * inv0, oacc[nf][1] * inv0};
        float2 o1 = {oacc[nf][2] * inv1, oacc[nf][3] * inv1};
        *(float2*)(O + i0) = o0;
        *(float2*)(O + i1) = o1;
        *(uint32_t*)(Oh + i0) = pack_h2(o0.x, o0.y);
        *(uint32_t*)(Oh + i1) = pack_h2(o1.x, o1.y);
    }
}

// ---------------- SwiGLU: G = silu(G) * U (fp32 in place + fp16 mirror) ----------------
__global__ void silu_mul_kernel(float* __restrict__ G, const float* __restrict__ U,
                                __half* __restrict__ Gh, int n4)
{
    const int i = blockIdx.x * blockDim.x + threadIdx.x;
    if (i >= n4) return;
    float4 g = ((const float4*)G)[i];
    float4 u = ((const float4*)U)[i];
    g.x = g.x / (1.f + __expf(-g.x)) * u.x;
    g.y = g.y / (1.f + __expf(-g.y)) * u.y;
    g.z = g.z / (1.f + __expf(-g.z)) * u.z;
    g.w = g.w / (1.f + __expf(-g.w)) * u.w;
    ((float4*)G)[i] = g;
    uint2 hp = make_uint2(pack_h2(g.x, g.y), pack_h2(g.z, g.w));
    ((uint2*)Gh)[i] = hp;
}

// ---------------- launcher ----------------
#define GEMM_SMEM 65536

extern "C" void kernel_launch(void* const* d_in, const int* in_sizes, int n_in,
                              void* d_out, int out_size)
{
    const float* data      = (const float*)d_in[0];
    const float* cosp      = (const float*)d_in[2];
    const float* sinp      = (const float*)d_in[3];
    const float* attn_norm = (const float*)d_in[4];
    const float* wq        = (const float*)d_in[5];
    const float* wk        = (const float*)d_in[6];
    const float* wv        = (const float*)d_in[7];
    const float* wo        = (const float*)d_in[8];
    const float* wq_a      = (const float*)d_in[9];
    const float* wq_b      = (const float*)d_in[10];
    const float* wk_a      = (const float*)d_in[11];
    const float* wk_b      = (const float*)d_in[12];
    const float* wv_a      = (const float*)d_in[13];
    const float* wv_b      = (const float*)d_in[14];
    const float* wo_a      = (const float*)d_in[15];
    const float* wo_b      = (const float*)d_in[16];
    const float* ffn_norm  = (const float*)d_in[17];
    const float* w1        = (const float*)d_in[18];
    const float* w2        = (const float*)d_in[19];
    const float* w3        = (const float*)d_in[20];
    const float* w1_a      = (const float*)d_in[21];
    const float* w1_b      = (const float*)d_in[22];
    const float* w2_a      = (const float*)d_in[23];
    const float* w2_b      = (const float*)d_in[24];
    const float* w3_a      = (const float*)d_in[25];
    const float* w3_b      = (const float*)d_in[26];
    float* out = (float*)d_out;

    float *h, *q, *k, *v, *attn, *res2, *gate, *up, *tmp;
    cudaGetSymbolAddress((void**)&h, g_h);
    cudaGetSymbolAddress((void**)&q, g_q);
    cudaGetSymbolAddress((void**)&k, g_k);
    cudaGetSymbolAddress((void**)&v, g_v);
    cudaGetSymbolAddress((void**)&attn, g_attn);
    cudaGetSymbolAddress((void**)&res2, g_res2);
    cudaGetSymbolAddress((void**)&gate, g_gate);
    cudaGetSymbolAddress((void**)&up, g_up);
    cudaGetSymbolAddress((void**)&tmp, g_tmp);

    __half *wq_h, *wk_h, *wv_h, *wo_h, *w1_h, *w3_h, *w2_h, *h_h, *attn_h, *gu_h;
    cudaGetSymbolAddress((void**)&wq_h, g_wq_h);
    cudaGetSymbolAddress((void**)&wk_h, g_wk_h);
    cudaGetSymbolAddress((void**)&wv_h, g_wv_h);
    cudaGetSymbolAddress((void**)&wo_h, g_wo_h);
    cudaGetSymbolAddress((void**)&w1_h, g_w1_h);
    cudaGetSymbolAddress((void**)&w3_h, g_w3_h);
    cudaGetSymbolAddress((void**)&w2_h, g_w2_h);
    cudaGetSymbolAddress((void**)&h_h, g_h_h);
    cudaGetSymbolAddress((void**)&attn_h, g_attn_h);
    cudaGetSymbolAddress((void**)&gu_h, g_gu_h);

    cudaFuncSetAttribute(flash16_kernel, cudaFuncAttributeMaxDynamicSharedMemorySize, FLASH_SMEM);
    cudaFuncSetAttribute(gemm_fp16, cudaFuncAttributeMaxDynamicSharedMemorySize, GEMM_SMEM);

    // ---- weight conversions (fp32 -> fp16) ----
    f2h_kernel<<<(DM * DM / 8) / 256, 256>>>(wq, wq_h, DM * DM / 8);
    f2h_kernel<<<(KVDIM * DM / 8) / 256, 256>>>(wk, wk_h, KVDIM * DM / 8);
    f2h_kernel<<<(KVDIM * DM / 8) / 256, 256>>>(wv, wv_h, KVDIM * DM / 8);
    f2h_kernel<<<(DM * DM / 8) / 256, 256>>>(wo, wo_h, DM * DM / 8);
    f2h_kernel<<<(FF * DM / 8) / 256, 256>>>(w1, w1_h, FF * DM / 8);
    f2h_kernel<<<(FF * DM / 8) / 256, 256>>>(w3, w3_h, FF * DM / 8);
    f2h_kernel<<<(DM * FF / 8) / 256, 256>>>(w2, w2_h, DM * FF / 8);

    // ---- attention block ----
    rmsnorm_kernel<<<SLEN, 256>>>(data, attn_norm, h, h_h, DM);

    lora_tmp_kernel<<<SLEN, 512>>>(h, wq_a, tmp, DM);
    gemm_fp16<<<dim3(SLEN / 128, DM / 128), 256, GEMM_SMEM>>>(h_h, wq_h, tmp, wq_b, nullptr, q, SLEN, DM, DM);
    rope_kernel<<<(SLEN * 32 * 64) / 256, 256>>>(q, cosp, sinp, 32, SLEN * 32 * 64);

    lora_tmp_kernel<<<SLEN, 512>>>(h, wk_a, tmp, DM);
    gemm_fp16<<<dim3(SLEN / 128, KVDIM / 128), 256, GEMM_SMEM>>>(h_h, wk_h, tmp, wk_b, nullptr, k, SLEN, KVDIM, DM);
    rope_kernel<<<(SLEN * 8 * 64) / 256, 256>>>(k, cosp, sinp, 8, SLEN * 8 * 64);

    lora_tmp_kernel<<<SLEN, 512>>>(h, wv_a, tmp, DM);
    gemm_fp16<<<dim3(SLEN / 128, KVDIM / 128), 256, GEMM_SMEM>>>(h_h, wv_h, tmp, wv_b, nullptr, v, SLEN, KVDIM, DM);

    flash16_kernel<<<dim3(SLEN / 128, 32), 256, FLASH_SMEM>>>(q, k, v, attn, attn_h);

    lora_tmp_kernel<<<SLEN, 512>>>(attn, wo_a, tmp, DM);
    gemm_fp16<<<dim3(SLEN / 128, DM / 128), 256, GEMM_SMEM>>>(attn_h, wo_h, tmp, wo_b, data, res2, SLEN, DM, DM);

    // ---- FFN block ----
    rmsnorm_kernel<<<SLEN, 256>>>(res2, ffn_norm, h, h_h, DM);

    lora_tmp_kernel<<<SLEN, 512>>>(h, w1_a, tmp, DM);
    gemm_fp16<<<dim3(SLEN / 128, FF / 128), 256, GEMM_SMEM>>>(h_h, w1_h, tmp, w1_b, nullptr, gate, SLEN, FF, DM);

    lora_tmp_kernel<<<SLEN, 512>>>(h, w3_a, tmp, DM);
    gemm_fp16<<<dim3(SLEN / 128, FF / 128), 256, GEMM_SMEM>>>(h_h, w3_h, tmp, w3_b, nullptr, up, SLEN, FF, DM);

    silu_mul_kernel<<<(SLEN * FF / 4) / 256, 256>>>(gate, up, gu_h, SLEN * FF / 4);

    lora_tmp_kernel<<<SLEN, 512>>>(gate, w2_a, tmp, FF);
    gemm_fp16<<<dim3(SLEN / 128, DM / 128), 256, GEMM_SMEM>>>(gu_h, w2_h, tmp, w2_b, res2, out, SLEN, DM, FF);
}